// round 14
// baseline (speedup 1.0000x reference)
#include <cuda_runtime.h>
#include <math.h>

// ---------------- constants ----------------
#define RMAX 8192
static constexpr float SDF_T = 5e-05f;
static constexpr float INV99 = 1.0f / 99.0f;

// ---------------- inter-kernel scratch ----------------
__device__ float g_acc_s[RMAX], g_acc_e[RMAX];
__device__ float g_nsdf_s[RMAX], g_nsdf_e[RMAX];
__device__ float g_csdf_s[RMAX], g_csdf_e[RMAX];
__device__ int   g_unfin_s[RMAX], g_unfin_e[RMAX];
__device__ float g_smin[RMAX], g_smax[RMAX];
__device__ int   g_mlist[RMAX];
__device__ int   g_nmasked;
__device__ int   g_flist[RMAX];
__device__ int   g_nfall;
__device__ int   g_seclist[RMAX];
__device__ int   g_seccount;
__device__ float g_zlo[RMAX], g_zhi[RMAX], g_slo[RMAX], g_shi[RMAX], g_zp[RMAX];
__device__ int   g_rlist0[RMAX];
__device__ int   g_rlist1[RMAX];
__device__ int   g_nplist[RMAX];
__device__ int   g_ecnt[64];

__global__ void init_kernel() {
    int t = threadIdx.x;
    if (t < 64) g_ecnt[t] = 0;
    if (t == 64) g_nmasked = 0;
    if (t == 65) g_seccount = 0;
    if (t == 66) g_nfall = 0;
}

// ---------------- f32x2 helpers ----------------
__device__ __forceinline__ unsigned long long pack2(float a, float b) {
    unsigned long long r;
    asm("mov.b64 %0, {%1, %2};" : "=l"(r) : "f"(a), "f"(b));
    return r;
}
__device__ __forceinline__ void unpack2(unsigned long long v, float& a, float& b) {
    asm("mov.b64 {%0, %1}, %2;" : "=f"(a), "=f"(b) : "l"(v));
}
__device__ __forceinline__ unsigned long long fma2(unsigned long long a,
                                                   unsigned long long b,
                                                   unsigned long long c) {
    unsigned long long d;
    asm("fma.rn.f32x2 %0, %1, %2, %3;" : "=l"(d) : "l"(a), "l"(b), "l"(c));
    return d;
}
__device__ __forceinline__ unsigned long long add2(unsigned long long a,
                                                   unsigned long long b) {
    unsigned long long d;
    asm("add.rn.f32x2 %0, %1, %2;" : "=l"(d) : "l"(a), "l"(b));
    return d;
}

__device__ __forceinline__ float tanh_fast(float x) {
    x = fminf(fmaxf(x, -15.f), 15.f);
    float e = __expf(2.f * x);
    return (e - 1.f) * __fdividef(1.f, e + 1.f);
}

// ---------------- batched SDF eval, P = 32 points, 1024 threads ----------------
// thread = (neuron pair) x (point half) x (k quarter). Serial k loop: 32 iters.
// 4 k-quarter partials combined in 3 sequential 32KB smem rounds (h1s reused).
__device__ __forceinline__ void sdf_eval32(
    const float* __restrict__ W1, const float* __restrict__ b1,
    const float* __restrict__ W2, const float* __restrict__ b2,
    const float* __restrict__ W3, float b3v,
    const float* pts, float* h1s, float* red, float* sdfv)
{
    const int tid = threadIdx.x;

    // ---- layer 1: 8192 entries / 1024 threads = 8 iters ----
#pragma unroll
    for (int it = 0; it < 8; ++it) {
        int idx = it * 1024 + tid;
        int k = idx >> 5;
        int p = idx & 31;
        float x = pts[p * 3 + 0], y = pts[p * 3 + 1], z = pts[p * 3 + 2];
        float v = fmaf(W1[k], x, fmaf(W1[256 + k], y, fmaf(W1[512 + k], z, b1[k])));
        h1s[idx] = tanh_fast(v);
    }
    __syncthreads();

    // ---- layer 2 ----
    const int kq  = tid >> 8;            // k quarter 0..3 (64 k's each)
    const int rem = tid & 255;
    const int half  = rem >> 7;          // point half
    const int npair = rem & 127;         // neurons 2*npair, 2*npair+1
    unsigned long long accA[8], accB[8];
#pragma unroll
    for (int q = 0; q < 8; ++q) { accA[q] = 0ull; accB[q] = 0ull; }

    const float2* W2p = reinterpret_cast<const float2*>(W2) + npair;
    const float* hbase = h1s + half * 16;
    const int kbase = kq << 6;
    const int kend  = kbase + 64;

    float2 w0[2], w1[2];
#pragma unroll
    for (int u = 0; u < 2; ++u) w0[u] = W2p[(kbase + u) * 128];
#pragma unroll
    for (int u = 0; u < 2; ++u) w1[u] = W2p[(kbase + 2 + u) * 128];

#pragma unroll 1
    for (int k0 = kbase; k0 < kend; k0 += 2) {
        float2 wn[2];
        int kp = k0 + 4;
        if (kp < kend) {
#pragma unroll
            for (int u = 0; u < 2; ++u) wn[u] = W2p[(kp + u) * 128];
        } else {
#pragma unroll
            for (int u = 0; u < 2; ++u) wn[u] = make_float2(0.f, 0.f);
        }
#pragma unroll
        for (int u = 0; u < 2; ++u) {
            unsigned long long wA = pack2(w0[u].x, w0[u].x);
            unsigned long long wB = pack2(w0[u].y, w0[u].y);
            const ulonglong2* h2 =
                reinterpret_cast<const ulonglong2*>(hbase + (k0 + u) * 32);
            ulonglong2 v0 = h2[0], v1 = h2[1], v2 = h2[2], v3 = h2[3];
            accA[0] = fma2(v0.x, wA, accA[0]); accB[0] = fma2(v0.x, wB, accB[0]);
            accA[1] = fma2(v0.y, wA, accA[1]); accB[1] = fma2(v0.y, wB, accB[1]);
            accA[2] = fma2(v1.x, wA, accA[2]); accB[2] = fma2(v1.x, wB, accB[2]);
            accA[3] = fma2(v1.y, wA, accA[3]); accB[3] = fma2(v1.y, wB, accB[3]);
            accA[4] = fma2(v2.x, wA, accA[4]); accB[4] = fma2(v2.x, wB, accB[4]);
            accA[5] = fma2(v2.y, wA, accA[5]); accB[5] = fma2(v2.y, wB, accB[5]);
            accA[6] = fma2(v3.x, wA, accA[6]); accB[6] = fma2(v3.x, wB, accB[6]);
            accA[7] = fma2(v3.y, wA, accA[7]); accB[7] = fma2(v3.y, wB, accB[7]);
        }
#pragma unroll
        for (int u = 0; u < 2; ++u) { w0[u] = w1[u]; w1[u] = wn[u]; }
    }

    // ---- combine 4 k-quarters: 3 sequential 32KB rounds through h1s ----
    __syncthreads();
    unsigned long long* part = reinterpret_cast<unsigned long long*>(h1s);
#pragma unroll
    for (int s = 1; s < 4; ++s) {
        if (kq == s) {
#pragma unroll
            for (int q = 0; q < 8; ++q) {
                part[q * 256 + rem]       = accA[q];
                part[(8 + q) * 256 + rem] = accB[q];
            }
        }
        __syncthreads();
        if (kq == 0) {
#pragma unroll
            for (int q = 0; q < 8; ++q) {
                accA[q] = add2(accA[q], part[q * 256 + rem]);
                accB[q] = add2(accB[q], part[(8 + q) * 256 + rem]);
            }
        }
        __syncthreads();
    }

    if (kq == 0) {
        // ---- layer 3 (threads 0..255; full warps) ----
        float2 b2v = reinterpret_cast<const float2*>(b2)[npair];
        float2 w3j = reinterpret_cast<const float2*>(W3)[npair];
        const int sub = (rem >> 5) & 3;
#pragma unroll
        for (int q = 0; q < 8; ++q) {
            float a0, a1, c0, c1;
            unpack2(accA[q], a0, a1);
            unpack2(accB[q], c0, c1);
            float m0 = tanh_fast(a0 + b2v.x) * w3j.x + tanh_fast(c0 + b2v.y) * w3j.y;
            float m1 = tanh_fast(a1 + b2v.x) * w3j.x + tanh_fast(c1 + b2v.y) * w3j.y;
#pragma unroll
            for (int off = 16; off; off >>= 1) {
                m0 += __shfl_down_sync(0xffffffffu, m0, off);
                m1 += __shfl_down_sync(0xffffffffu, m1, off);
            }
            if ((rem & 31) == 0) {
                int p0 = half * 16 + 2 * q;
                red[p0 * 4 + sub] = m0;
                red[(p0 + 1) * 4 + sub] = m1;
            }
        }
    }
    __syncthreads();
    if (tid < 32) {
        float s = red[tid * 4 + 0] + red[tid * 4 + 1] + red[tid * 4 + 2] + red[tid * 4 + 3];
        float x = pts[tid * 3 + 0], y = pts[tid * 3 + 1], z = pts[tid * 3 + 2];
        float base = sqrtf(fmaf(x, x, fmaf(y, y, fmaf(z, z, 1e-12f)))) - 0.6f;
        sdfv[tid] = base + 0.05f * (s + b3v);
    }
    __syncthreads();
}

// ---------------- K1: ray init + eval both endpoints + seed list0 ----------------
__global__ __launch_bounds__(1024)
void k1_init_eval(const float* __restrict__ cam_in, const float* __restrict__ ray_in,
                  const float* __restrict__ W1, const float* __restrict__ b1,
                  const float* __restrict__ W2, const float* __restrict__ b2,
                  const float* __restrict__ W3, const float* __restrict__ b3,
                  int R)
{
    __shared__ __align__(16) float h1s[8192];
    __shared__ float red[128];
    __shared__ float pts[96];
    __shared__ float sdfv[32];
    __shared__ float sa[16], se[16];
    __shared__ int   srm[16];

    const int tid = threadIdx.x;
    const int base = blockIdx.x * 16;
    const float b3v = b3[0];

    if (tid < 16) {
        int r = base + tid;
        int rc = (r < R) ? r : (R - 1);
        float cx = cam_in[rc*3+0], cy = cam_in[rc*3+1], cz = cam_in[rc*3+2];
        float rx = ray_in[rc*3+0], ry = ray_in[rc*3+1], rz = ray_in[rc*3+2];
        float dt = rx*cx + ry*cy + rz*cz;
        float cc = cx*cx + cy*cy + cz*cz;
        float under = dt*dt - (cc - 1.0f);
        int mi = (under > 0.f) ? 1 : 0;
        float sq = sqrtf(mi ? under : 1.0f);
        float i0 = mi ? fmaxf(-sq - dt, 0.f) : 0.f;
        float i1 = mi ? fmaxf( sq - dt, 0.f) : 0.f;
        if (r < R) {
            g_acc_s[r] = i0; g_acc_e[r] = i1;
            g_unfin_s[r] = mi; g_unfin_e[r] = mi;
            g_nsdf_s[r] = 0.f; g_nsdf_e[r] = 0.f;
            if (mi) {
                int pos = atomicAdd(&g_ecnt[0], 1);
                g_rlist0[pos] = r;
            }
        }
        sa[tid] = i0; se[tid] = i1;
        srm[tid] = (r < R && mi) ? r : -1;
    }
    __syncthreads();
    if (tid < 32) {
        int g = tid >> 1;
        int r = base + g; if (r >= R) r = R - 1;
        float a = (tid & 1) ? se[g] : sa[g];
        pts[tid*3+0] = fmaf(a, ray_in[r*3+0], cam_in[r*3+0]);
        pts[tid*3+1] = fmaf(a, ray_in[r*3+1], cam_in[r*3+1]);
        pts[tid*3+2] = fmaf(a, ray_in[r*3+2], cam_in[r*3+2]);
    }
    __syncthreads();
    sdf_eval32(W1, b1, W2, b2, W3, b3v, pts, h1s, red, sdfv);
    if (tid < 16) {
        int r = srm[tid];
        if (r >= 0) {
            g_nsdf_s[r] = sdfv[tid * 2 + 0];
            g_nsdf_e[r] = sdfv[tid * 2 + 1];
        }
    }
}

// ---------------- E1: gating + advance + eval + np backstep ----------------
__global__ __launch_bounds__(1024)
void e1_kernel(const float* __restrict__ cam_in, const float* __restrict__ ray_in,
               const float* __restrict__ W1, const float* __restrict__ b1,
               const float* __restrict__ W2, const float* __restrict__ b2,
               const float* __restrict__ W3, const float* __restrict__ b3,
               int it)
{
    const int cnt = g_ecnt[it];
    const int base = blockIdx.x * 16;
    if (base >= cnt) return;
    const int* rl = (it & 1) ? g_rlist1 : g_rlist0;
    int* rl_next  = (it & 1) ? g_rlist0 : g_rlist1;

    __shared__ __align__(16) float h1s[8192];
    __shared__ float red[128];
    __shared__ float pts[96];
    __shared__ float sdfv[32];
    __shared__ float sa[16], se[16];
    __shared__ float scs[16], sce[16];
    __shared__ int   srr[16], sus[16], sue[16];

    const int tid = threadIdx.x;
    const float b3v = b3[0];
    const int apply_lt = (it > 0) ? 1 : 0;

    if (tid < 16) {
        int i = base + tid;
        int valid = (i < cnt) ? 1 : 0;
        int r = rl[valid ? i : (cnt - 1)];
        float as = g_acc_s[r], ae = g_acc_e[r];
        int lt = apply_lt ? ((as < ae) ? 1 : 0) : 1;
        int us0 = g_unfin_s[r] & lt & valid;
        int ue0 = g_unfin_e[r] & lt & valid;

        float cs = us0 ? g_nsdf_s[r] : 0.f;
        cs = (cs <= SDF_T) ? 0.f : cs;
        int us = us0 & ((cs > SDF_T) ? 1 : 0);
        float ce = ue0 ? g_nsdf_e[r] : 0.f;
        ce = (ce <= SDF_T) ? 0.f : ce;
        int ue = ue0 & ((ce > SDF_T) ? 1 : 0);

        float nas = as + cs, nae = ae - ce;
        if (valid) {
            g_unfin_s[r] = us; g_unfin_e[r] = ue;
            g_csdf_s[r] = cs; g_csdf_e[r] = ce;
            g_acc_s[r] = nas; g_acc_e[r] = nae;
            if (us | ue) {
                int pos = atomicAdd(&g_ecnt[it + 1], 1);
                rl_next[pos] = r;
            }
        }
        sa[tid] = nas; se[tid] = nae;
        scs[tid] = cs; sce[tid] = ce;
        srr[tid] = valid ? r : -1;
        sus[tid] = us; sue[tid] = ue;
    }
    __syncthreads();
    if (tid < 32) {
        int g = tid >> 1;
        int r = srr[g]; if (r < 0) r = rl[cnt - 1];
        float a = (tid & 1) ? se[g] : sa[g];
        pts[tid*3+0] = fmaf(a, ray_in[r*3+0], cam_in[r*3+0]);
        pts[tid*3+1] = fmaf(a, ray_in[r*3+1], cam_in[r*3+1]);
        pts[tid*3+2] = fmaf(a, ray_in[r*3+2], cam_in[r*3+2]);
    }
    __syncthreads();
    sdf_eval32(W1, b1, W2, b2, W3, b3v, pts, h1s, red, sdfv);
    if (tid < 16) {
        int r = srr[tid];
        if (r >= 0) {
            int nps = 0, npe = 0;
            if (sus[tid]) {
                float ns = sdfv[tid*2+0];
                g_nsdf_s[r] = ns;
                if (ns < 0.f) { nps = 1; g_acc_s[r] = sa[tid] - 0.5f * scs[tid]; }
            }
            if (sue[tid]) {
                float ne = sdfv[tid*2+1];
                g_nsdf_e[r] = ne;
                if (ne < 0.f) { npe = 1; g_acc_e[r] = se[tid] + 0.5f * sce[tid]; }
            }
            if (nps | npe) {
                int pos = atomicAdd(&g_ecnt[32 + it], 1);
                g_nplist[pos] = r | (nps << 16) | (npe << 17);
            }
        }
    }
}

// ---------------- E2: line-search re-eval over np rays ----------------
__global__ __launch_bounds__(1024)
void e2_kernel(const float* __restrict__ cam_in, const float* __restrict__ ray_in,
               const float* __restrict__ W1, const float* __restrict__ b1,
               const float* __restrict__ W2, const float* __restrict__ b2,
               const float* __restrict__ W3, const float* __restrict__ b3,
               int it)
{
    const int cnt = g_ecnt[32 + it];
    const int base = blockIdx.x * 16;
    if (base >= cnt) return;

    __shared__ __align__(16) float h1s[8192];
    __shared__ float red[128];
    __shared__ float pts[96];
    __shared__ float sdfv[32];
    __shared__ float sa[16], se[16];
    __shared__ int   sitem[16];

    const int tid = threadIdx.x;
    const float b3v = b3[0];

    if (tid < 16) {
        int i = base + tid;
        int valid = (i < cnt) ? 1 : 0;
        int item = g_nplist[valid ? i : (cnt - 1)];
        int r = item & 0xFFFF;
        sitem[tid] = valid ? item : -1;
        sa[tid] = g_acc_s[r];
        se[tid] = g_acc_e[r];
    }
    __syncthreads();
    if (tid < 32) {
        int g = tid >> 1;
        int item = sitem[g];
        int r = (item >= 0) ? (item & 0xFFFF) : (g_nplist[cnt - 1] & 0xFFFF);
        float a = (tid & 1) ? se[g] : sa[g];
        pts[tid*3+0] = fmaf(a, ray_in[r*3+0], cam_in[r*3+0]);
        pts[tid*3+1] = fmaf(a, ray_in[r*3+1], cam_in[r*3+1]);
        pts[tid*3+2] = fmaf(a, ray_in[r*3+2], cam_in[r*3+2]);
    }
    __syncthreads();
    sdf_eval32(W1, b1, W2, b2, W3, b3v, pts, h1s, red, sdfv);
    if (tid < 16) {
        int item = sitem[tid];
        if (item >= 0) {
            int r = item & 0xFFFF;
            if (item & 0x10000) g_nsdf_s[r] = sdfv[tid*2+0];
            if (item & 0x20000) g_nsdf_e[r] = sdfv[tid*2+1];
        }
    }
}

// ---------------- final: mask + defaults ----------------
__global__ __launch_bounds__(256)
void k_final(const float* __restrict__ cam_in, const float* __restrict__ ray_in,
             float* __restrict__ out, int R)
{
    int r = blockIdx.x * 256 + threadIdx.x;
    if (r >= R) return;
    float as = g_acc_s[r], ae = g_acc_e[r];
    int us = g_unfin_s[r] & ((as < ae) ? 1 : 0);
    float cs = us ? g_nsdf_s[r] : 0.f;
    cs = (cs <= SDF_T) ? 0.f : cs;
    int mask = us & ((cs > SDF_T) ? 1 : 0);
    g_smin[r] = as; g_smax[r] = ae;
    if (mask) {
        int pos = atomicAdd(&g_nmasked, 1);
        g_mlist[pos] = r;
    }
    float cx = cam_in[r*3+0], cy = cam_in[r*3+1], cz = cam_in[r*3+2];
    float rx = ray_in[r*3+0], ry = ray_in[r*3+1], rz = ray_in[r*3+2];
    out[r*3+0] = fmaf(as, rx, cx);
    out[r*3+1] = fmaf(as, ry, cy);
    out[r*3+2] = fmaf(as, rz, cz);
    out[R*3+r] = (as < ae) ? 1.f : 0.f;
    out[R*4+r] = as;
}

// ---------------- sampler prepass: 4 masked rays x 8 samples per eval ----------------
__global__ __launch_bounds__(1024)
void prepass_kernel(const float* __restrict__ cam_in, const float* __restrict__ ray_in,
                    const float* __restrict__ W1, const float* __restrict__ b1,
                    const float* __restrict__ W2, const float* __restrict__ b2,
                    const float* __restrict__ W3, const float* __restrict__ b3)
{
    const int nmask = g_nmasked;
    const int g = blockIdx.x;
    if (g * 4 >= nmask) return;

    __shared__ __align__(16) float h1s[8192];
    __shared__ float red[128];
    __shared__ float pts[96];
    __shared__ float sdfv[32];

    const int tid = threadIdx.x;
    const float b3v = b3[0];
    if (tid < 32) {
        int li = g * 4 + (tid >> 3);
        int lic = (li < nmask) ? li : (nmask - 1);
        int r = g_mlist[lic];
        float smin = g_smin[r];
        float dz = g_smax[r] - smin;
        int i = tid & 7;
        float z = fmaf(dz, (float)i * INV99, smin);
        pts[tid*3+0] = fmaf(z, ray_in[r*3+0], cam_in[r*3+0]);
        pts[tid*3+1] = fmaf(z, ray_in[r*3+1], cam_in[r*3+1]);
        pts[tid*3+2] = fmaf(z, ray_in[r*3+2], cam_in[r*3+2]);
    }
    __syncthreads();
    sdf_eval32(W1, b1, W2, b2, W3, b3v, pts, h1s, red, sdfv);
    if (tid < 32) {
        bool neg = (sdfv[tid] < 0.f);
        unsigned ball = __ballot_sync(0xffffffffu, neg);
        if ((tid & 7) == 0) {
            int j = tid >> 3;
            int li = g * 4 + j;
            if (li < nmask) {
                int r = g_mlist[li];
                unsigned sub = (ball >> (j * 8)) & 0xFFu;
                int q = sub ? (__ffs(sub) - 1) : 0;
                if (sub && q >= 1) {
                    float smin = g_smin[r];
                    float dz = g_smax[r] - smin;
                    float zlo = fmaf(dz, (float)(q - 1) * INV99, smin);
                    float zhi = fmaf(dz, (float)q * INV99, smin);
                    float slo = sdfv[j * 8 + q - 1];
                    float shi = sdfv[j * 8 + q];
                    float den = shi - slo; if (fabsf(den) <= 1e-12f) den = 1e-12f;
                    float zp = -slo * (zhi - zlo) / den + zlo;
                    g_zlo[r] = zlo; g_zhi[r] = zhi;
                    g_slo[r] = slo; g_shi[r] = shi; g_zp[r] = zp;
                    int pos = atomicAdd(&g_seccount, 1);
                    g_seclist[pos] = r;
                } else {
                    int pos = atomicAdd(&g_nfall, 1);
                    g_flist[pos] = r;
                }
            }
        }
    }
}

// ---------------- sampler fallback: full chunked scan ----------------
__global__ __launch_bounds__(1024)
void fallback_kernel(const float* __restrict__ cam_in, const float* __restrict__ ray_in,
                     const float* __restrict__ W1, const float* __restrict__ b1,
                     const float* __restrict__ W2, const float* __restrict__ b2,
                     const float* __restrict__ W3, const float* __restrict__ b3,
                     float* __restrict__ out, int R)
{
    const int li = blockIdx.x;
    if (li >= g_nfall) return;
    const int r = g_flist[li];

    __shared__ __align__(16) float h1s[8192];
    __shared__ float red[128];
    __shared__ float pts[96];
    __shared__ float sdfv[32];
    __shared__ float s_all[100];
    __shared__ float s_cr[6];
    __shared__ int   s_found;

    const int tid = threadIdx.x;
    const float b3v = b3[0];
    if (tid < 6)
        s_cr[tid] = (tid < 3) ? cam_in[r * 3 + tid] : ray_in[r * 3 + tid - 3];
    if (tid == 0) s_found = -1;
    const float smin = g_smin[r];
    const float dz = g_smax[r] - smin;
    __syncthreads();

    for (int c = 0; c < 4; ++c) {
        const int cbase = c * 32;
        const int cnt = (100 - cbase < 32) ? (100 - cbase) : 32;
        if (tid < 32) {
            int i = cbase + tid; if (i > 99) i = 99;
            float z = fmaf(dz, (float)i * INV99, smin);
            pts[tid*3+0] = fmaf(z, s_cr[3], s_cr[0]);
            pts[tid*3+1] = fmaf(z, s_cr[4], s_cr[1]);
            pts[tid*3+2] = fmaf(z, s_cr[5], s_cr[2]);
        }
        __syncthreads();
        sdf_eval32(W1, b1, W2, b2, W3, b3v, pts, h1s, red, sdfv);
        if (tid < 32) {
            if (tid < cnt) s_all[cbase + tid] = sdfv[tid];
            bool neg = (tid < cnt) && (sdfv[tid] < 0.f);
            unsigned m = __ballot_sync(0xffffffffu, neg);
            if (tid == 0 && m) s_found = cbase + (__ffs(m) - 1);
        }
        __syncthreads();
        if (s_found >= 0) break;
    }

    if (tid == 0) {
        int ind;
        if (s_found >= 0) {
            ind = s_found;
        } else {
            ind = 99;
            for (int i = 0; i < 100; ++i)
                if (s_all[i] == 0.f) { ind = i; break; }
        }
        int il = (ind >= 1) ? (ind - 1) : 99;
        if (il > ind && s_found >= 0) il = 0;
        float zlo = fmaf(dz, (float)il  * INV99, smin);
        float zhi = fmaf(dz, (float)ind * INV99, smin);
        float slo = s_all[il], shi = s_all[ind];
        if (shi < 0.f) {
            float den = shi - slo; if (fabsf(den) <= 1e-12f) den = 1e-12f;
            float zp = -slo * (zhi - zlo) / den + zlo;
            g_zlo[r] = zlo; g_zhi[r] = zhi; g_slo[r] = slo; g_shi[r] = shi; g_zp[r] = zp;
            int pos = atomicAdd(&g_seccount, 1);
            g_seclist[pos] = r;
        } else {
            float dist = zhi;
            out[r*3+0] = fmaf(dist, s_cr[3], s_cr[0]);
            out[r*3+1] = fmaf(dist, s_cr[4], s_cr[1]);
            out[r*3+2] = fmaf(dist, s_cr[5], s_cr[2]);
            out[R*3+r] = 0.f;
            out[R*4+r] = dist;
        }
    }
}

// ---------------- batched secant: 32 rays per block ----------------
__global__ __launch_bounds__(1024)
void secant_kernel(const float* __restrict__ cam_in, const float* __restrict__ ray_in,
                   const float* __restrict__ W1, const float* __restrict__ b1,
                   const float* __restrict__ W2, const float* __restrict__ b2,
                   const float* __restrict__ W3, const float* __restrict__ b3,
                   float* __restrict__ out, int R)
{
    const int base = blockIdx.x * 32;
    if (base >= g_seccount) return;

    __shared__ __align__(16) float h1s[8192];
    __shared__ float red[128];
    __shared__ float pts[96];
    __shared__ float sdfv[32];
    __shared__ float s_cr[32][6];
    __shared__ float s_zlo[32], s_zhi[32], s_slo[32], s_shi[32], s_zp[32];
    __shared__ int   s_r[32];
    __shared__ int   s_n;

    const int tid = threadIdx.x;
    const float b3v = b3[0];
    if (tid == 0) {
        int c = g_seccount - base;
        s_n = (c < 32) ? c : 32;
    }
    __syncthreads();
    const int n = s_n;
    if (tid < 32) {
        int li = (tid < n) ? tid : 0;
        int r = g_seclist[base + li];
        s_r[tid] = (tid < n) ? r : -1;
        s_zlo[tid] = g_zlo[r]; s_zhi[tid] = g_zhi[r];
        s_slo[tid] = g_slo[r]; s_shi[tid] = g_shi[r];
        s_zp[tid]  = g_zp[r];
        s_cr[tid][0] = cam_in[r*3+0]; s_cr[tid][1] = cam_in[r*3+1]; s_cr[tid][2] = cam_in[r*3+2];
        s_cr[tid][3] = ray_in[r*3+0]; s_cr[tid][4] = ray_in[r*3+1]; s_cr[tid][5] = ray_in[r*3+2];
    }
    __syncthreads();

    for (int it = 0; it < 8; ++it) {
        if (tid < 32) {
            float zp = s_zp[tid];
            pts[tid*3+0] = fmaf(zp, s_cr[tid][3], s_cr[tid][0]);
            pts[tid*3+1] = fmaf(zp, s_cr[tid][4], s_cr[tid][1]);
            pts[tid*3+2] = fmaf(zp, s_cr[tid][5], s_cr[tid][2]);
        }
        __syncthreads();
        sdf_eval32(W1, b1, W2, b2, W3, b3v, pts, h1s, red, sdfv);
        if (tid < 32) {
            float mid = sdfv[tid];
            if (mid > 0.f) { s_zlo[tid] = s_zp[tid]; s_slo[tid] = mid; }
            if (mid < 0.f) { s_zhi[tid] = s_zp[tid]; s_shi[tid] = mid; }
            float den = s_shi[tid] - s_slo[tid];
            if (fabsf(den) <= 1e-12f) den = 1e-12f;
            s_zp[tid] = -s_slo[tid] * (s_zhi[tid] - s_zlo[tid]) / den + s_zlo[tid];
        }
        __syncthreads();
    }

    if (tid < n) {
        int r = s_r[tid];
        float dist = s_zp[tid];
        out[r*3+0] = fmaf(dist, s_cr[tid][3], s_cr[tid][0]);
        out[r*3+1] = fmaf(dist, s_cr[tid][4], s_cr[tid][1]);
        out[r*3+2] = fmaf(dist, s_cr[tid][5], s_cr[tid][2]);
        out[R*3+r] = 1.f;
        out[R*4+r] = dist;
    }
}

// ---------------- launch ----------------
extern "C" void kernel_launch(void* const* d_in, const int* in_sizes, int n_in,
                              void* d_out, int out_size)
{
    const float* cam  = (const float*)d_in[0];
    const float* rays = (const float*)d_in[1];
    // d_in[2] = object_mask (unused by the eval-mode forward)
    const float* W1 = (const float*)d_in[3];
    const float* b1 = (const float*)d_in[4];
    const float* W2 = (const float*)d_in[5];
    const float* b2 = (const float*)d_in[6];
    const float* W3 = (const float*)d_in[7];
    const float* b3 = (const float*)d_in[8];
    int R = in_sizes[0] / 3;
    if (R > RMAX) R = RMAX;
    float* out = (float*)d_out;

    const int nb  = (R + 255) / 256;
    const int n16 = (R + 15) / 16;

    init_kernel<<<1, 128>>>();
    k1_init_eval<<<n16, 1024>>>(cam, rays, W1, b1, W2, b2, W3, b3, R);
    for (int it = 0; it < 10; ++it) {
        e1_kernel<<<n16, 1024>>>(cam, rays, W1, b1, W2, b2, W3, b3, it);
        e2_kernel<<<n16, 1024>>>(cam, rays, W1, b1, W2, b2, W3, b3, it);
    }
    k_final<<<nb, 256>>>(cam, rays, out, R);
    prepass_kernel<<<(R + 3) / 4, 1024>>>(cam, rays, W1, b1, W2, b2, W3, b3);
    fallback_kernel<<<R, 1024>>>(cam, rays, W1, b1, W2, b2, W3, b3, out, R);
    secant_kernel<<<(R + 31) / 32, 1024>>>(cam, rays, W1, b1, W2, b2, W3, b3, out, R);
}

// round 15
// speedup vs baseline: 1.0530x; 1.0530x over previous
#include <cuda_runtime.h>
#include <math.h>

// ---------------- constants ----------------
#define RMAX 8192
static constexpr float SDF_T = 5e-05f;
static constexpr float INV99 = 1.0f / 99.0f;

// ---------------- inter-kernel scratch ----------------
__device__ float g_acc_s[RMAX], g_acc_e[RMAX];
__device__ float g_nsdf_s[RMAX], g_nsdf_e[RMAX];
__device__ float g_csdf_s[RMAX], g_csdf_e[RMAX];
__device__ int   g_unfin_s[RMAX], g_unfin_e[RMAX];
__device__ float g_smin[RMAX], g_smax[RMAX];
__device__ int   g_mlist[RMAX];
__device__ int   g_nmasked;
__device__ int   g_flist[RMAX];
__device__ int   g_nfall;
__device__ int   g_seclist[RMAX];
__device__ int   g_seccount;
__device__ float g_zlo[RMAX], g_zhi[RMAX], g_slo[RMAX], g_shi[RMAX], g_zp[RMAX];
__device__ int   g_rlist0[RMAX];
__device__ int   g_rlist1[RMAX];
__device__ int   g_nplist[RMAX];
__device__ int   g_ecnt[64];

__global__ void init_kernel() {
    int t = threadIdx.x;
    if (t < 64) g_ecnt[t] = 0;
    if (t == 64) g_nmasked = 0;
    if (t == 65) g_seccount = 0;
    if (t == 66) g_nfall = 0;
}

// ---------------- f32x2 helpers ----------------
__device__ __forceinline__ unsigned long long pack2(float a, float b) {
    unsigned long long r;
    asm("mov.b64 %0, {%1, %2};" : "=l"(r) : "f"(a), "f"(b));
    return r;
}
__device__ __forceinline__ void unpack2(unsigned long long v, float& a, float& b) {
    asm("mov.b64 {%0, %1}, %2;" : "=f"(a), "=f"(b) : "l"(v));
}
__device__ __forceinline__ unsigned long long fma2(unsigned long long a,
                                                   unsigned long long b,
                                                   unsigned long long c) {
    unsigned long long d;
    asm("fma.rn.f32x2 %0, %1, %2, %3;" : "=l"(d) : "l"(a), "l"(b), "l"(c));
    return d;
}
__device__ __forceinline__ unsigned long long add2(unsigned long long a,
                                                   unsigned long long b) {
    unsigned long long d;
    asm("add.rn.f32x2 %0, %1, %2;" : "=l"(d) : "l"(a), "l"(b));
    return d;
}

__device__ __forceinline__ float tanh_fast(float x) {
    x = fminf(fmaxf(x, -15.f), 15.f);
    float e = __expf(2.f * x);
    return (e - 1.f) * __fdividef(1.f, e + 1.f);
}

// ---------------- batched SDF eval, P = 32 points, NT threads ----------------
// NT=512: k-half split (throughput kernels, 2 blocks/SM).
// NT=1024: k-quarter split (latency kernels, shortest critical path).
template<int NT>
__device__ __forceinline__ void sdf_eval32(
    const float* __restrict__ W1, const float* __restrict__ b1,
    const float* __restrict__ W2, const float* __restrict__ b2,
    const float* __restrict__ W3, float b3v,
    const float* pts, float* h1s, float* red, float* sdfv)
{
    const int tid = threadIdx.x;

    // ---- layer 1 ----
#pragma unroll
    for (int it = 0; it < 8192 / NT; ++it) {
        int idx = it * NT + tid;
        int k = idx >> 5;
        int p = idx & 31;
        float x = pts[p * 3 + 0], y = pts[p * 3 + 1], z = pts[p * 3 + 2];
        float v = fmaf(W1[k], x, fmaf(W1[256 + k], y, fmaf(W1[512 + k], z, b1[k])));
        h1s[idx] = tanh_fast(v);
    }
    __syncthreads();

    // ---- layer 2 ----
    constexpr int KSPLIT = NT / 256;          // 2 or 4
    constexpr int KLEN   = 256 / KSPLIT;      // 128 or 64
    const int kq  = tid >> 8;                 // k segment
    const int rem = tid & 255;
    const int half  = rem >> 7;               // point half
    const int npair = rem & 127;              // neurons 2*npair, 2*npair+1
    unsigned long long accA[8], accB[8];
#pragma unroll
    for (int q = 0; q < 8; ++q) { accA[q] = 0ull; accB[q] = 0ull; }

    const float2* W2p = reinterpret_cast<const float2*>(W2) + npair;
    const float* hbase = h1s + half * 16;
    const int kbase = kq * KLEN;
    const int kend  = kbase + KLEN;

    float2 w0[2], w1[2];
#pragma unroll
    for (int u = 0; u < 2; ++u) w0[u] = W2p[(kbase + u) * 128];
#pragma unroll
    for (int u = 0; u < 2; ++u) w1[u] = W2p[(kbase + 2 + u) * 128];

#pragma unroll 1
    for (int k0 = kbase; k0 < kend; k0 += 2) {
        float2 wn[2];
        int kp = k0 + 4;
        if (kp < kend) {
#pragma unroll
            for (int u = 0; u < 2; ++u) wn[u] = W2p[(kp + u) * 128];
        } else {
#pragma unroll
            for (int u = 0; u < 2; ++u) wn[u] = make_float2(0.f, 0.f);
        }
#pragma unroll
        for (int u = 0; u < 2; ++u) {
            unsigned long long wA = pack2(w0[u].x, w0[u].x);
            unsigned long long wB = pack2(w0[u].y, w0[u].y);
            const ulonglong2* h2 =
                reinterpret_cast<const ulonglong2*>(hbase + (k0 + u) * 32);
            ulonglong2 v0 = h2[0], v1 = h2[1], v2 = h2[2], v3 = h2[3];
            accA[0] = fma2(v0.x, wA, accA[0]); accB[0] = fma2(v0.x, wB, accB[0]);
            accA[1] = fma2(v0.y, wA, accA[1]); accB[1] = fma2(v0.y, wB, accB[1]);
            accA[2] = fma2(v1.x, wA, accA[2]); accB[2] = fma2(v1.x, wB, accB[2]);
            accA[3] = fma2(v1.y, wA, accA[3]); accB[3] = fma2(v1.y, wB, accB[3]);
            accA[4] = fma2(v2.x, wA, accA[4]); accB[4] = fma2(v2.x, wB, accB[4]);
            accA[5] = fma2(v2.y, wA, accA[5]); accB[5] = fma2(v2.y, wB, accB[5]);
            accA[6] = fma2(v3.x, wA, accA[6]); accB[6] = fma2(v3.x, wB, accB[6]);
            accA[7] = fma2(v3.y, wA, accA[7]); accB[7] = fma2(v3.y, wB, accB[7]);
        }
#pragma unroll
        for (int u = 0; u < 2; ++u) { w0[u] = w1[u]; w1[u] = wn[u]; }
    }

    // ---- combine k segments through smem (h1s reused; 32KB per round) ----
    __syncthreads();
    unsigned long long* part = reinterpret_cast<unsigned long long*>(h1s);
#pragma unroll
    for (int s = 1; s < KSPLIT; ++s) {
        if (kq == s) {
#pragma unroll
            for (int q = 0; q < 8; ++q) {
                part[q * 256 + rem]       = accA[q];
                part[(8 + q) * 256 + rem] = accB[q];
            }
        }
        __syncthreads();
        if (kq == 0) {
#pragma unroll
            for (int q = 0; q < 8; ++q) {
                accA[q] = add2(accA[q], part[q * 256 + rem]);
                accB[q] = add2(accB[q], part[(8 + q) * 256 + rem]);
            }
        }
        __syncthreads();
    }

    if (kq == 0) {
        // ---- layer 3 (threads 0..255; full warps) ----
        float2 b2v = reinterpret_cast<const float2*>(b2)[npair];
        float2 w3j = reinterpret_cast<const float2*>(W3)[npair];
        const int sub = (rem >> 5) & 3;
#pragma unroll
        for (int q = 0; q < 8; ++q) {
            float a0, a1, c0, c1;
            unpack2(accA[q], a0, a1);
            unpack2(accB[q], c0, c1);
            float m0 = tanh_fast(a0 + b2v.x) * w3j.x + tanh_fast(c0 + b2v.y) * w3j.y;
            float m1 = tanh_fast(a1 + b2v.x) * w3j.x + tanh_fast(c1 + b2v.y) * w3j.y;
#pragma unroll
            for (int off = 16; off; off >>= 1) {
                m0 += __shfl_down_sync(0xffffffffu, m0, off);
                m1 += __shfl_down_sync(0xffffffffu, m1, off);
            }
            if ((rem & 31) == 0) {
                int p0 = half * 16 + 2 * q;
                red[p0 * 4 + sub] = m0;
                red[(p0 + 1) * 4 + sub] = m1;
            }
        }
    }
    __syncthreads();
    if (tid < 32) {
        float s = red[tid * 4 + 0] + red[tid * 4 + 1] + red[tid * 4 + 2] + red[tid * 4 + 3];
        float x = pts[tid * 3 + 0], y = pts[tid * 3 + 1], z = pts[tid * 3 + 2];
        float base = sqrtf(fmaf(x, x, fmaf(y, y, fmaf(z, z, 1e-12f)))) - 0.6f;
        sdfv[tid] = base + 0.05f * (s + b3v);
    }
    __syncthreads();
}

// ---------------- K1: ray init + eval both endpoints + seed list0 (512thr) ----------------
__global__ __launch_bounds__(512)
void k1_init_eval(const float* __restrict__ cam_in, const float* __restrict__ ray_in,
                  const float* __restrict__ W1, const float* __restrict__ b1,
                  const float* __restrict__ W2, const float* __restrict__ b2,
                  const float* __restrict__ W3, const float* __restrict__ b3,
                  int R)
{
    __shared__ __align__(16) float h1s[8192];
    __shared__ float red[128];
    __shared__ float pts[96];
    __shared__ float sdfv[32];
    __shared__ float sa[16], se[16];
    __shared__ int   srm[16];

    const int tid = threadIdx.x;
    const int base = blockIdx.x * 16;
    const float b3v = b3[0];

    if (tid < 16) {
        int r = base + tid;
        int rc = (r < R) ? r : (R - 1);
        float cx = cam_in[rc*3+0], cy = cam_in[rc*3+1], cz = cam_in[rc*3+2];
        float rx = ray_in[rc*3+0], ry = ray_in[rc*3+1], rz = ray_in[rc*3+2];
        float dt = rx*cx + ry*cy + rz*cz;
        float cc = cx*cx + cy*cy + cz*cz;
        float under = dt*dt - (cc - 1.0f);
        int mi = (under > 0.f) ? 1 : 0;
        float sq = sqrtf(mi ? under : 1.0f);
        float i0 = mi ? fmaxf(-sq - dt, 0.f) : 0.f;
        float i1 = mi ? fmaxf( sq - dt, 0.f) : 0.f;
        if (r < R) {
            g_acc_s[r] = i0; g_acc_e[r] = i1;
            g_unfin_s[r] = mi; g_unfin_e[r] = mi;
            g_nsdf_s[r] = 0.f; g_nsdf_e[r] = 0.f;
            if (mi) {
                int pos = atomicAdd(&g_ecnt[0], 1);
                g_rlist0[pos] = r;
            }
        }
        sa[tid] = i0; se[tid] = i1;
        srm[tid] = (r < R && mi) ? r : -1;
    }
    __syncthreads();
    if (tid < 32) {
        int g = tid >> 1;
        int r = base + g; if (r >= R) r = R - 1;
        float a = (tid & 1) ? se[g] : sa[g];
        pts[tid*3+0] = fmaf(a, ray_in[r*3+0], cam_in[r*3+0]);
        pts[tid*3+1] = fmaf(a, ray_in[r*3+1], cam_in[r*3+1]);
        pts[tid*3+2] = fmaf(a, ray_in[r*3+2], cam_in[r*3+2]);
    }
    __syncthreads();
    sdf_eval32<512>(W1, b1, W2, b2, W3, b3v, pts, h1s, red, sdfv);
    if (tid < 16) {
        int r = srm[tid];
        if (r >= 0) {
            g_nsdf_s[r] = sdfv[tid * 2 + 0];
            g_nsdf_e[r] = sdfv[tid * 2 + 1];
        }
    }
}

// ---------------- E1: gating + advance + eval + np backstep (512thr) ----------------
__global__ __launch_bounds__(512)
void e1_kernel(const float* __restrict__ cam_in, const float* __restrict__ ray_in,
               const float* __restrict__ W1, const float* __restrict__ b1,
               const float* __restrict__ W2, const float* __restrict__ b2,
               const float* __restrict__ W3, const float* __restrict__ b3,
               int it)
{
    const int cnt = g_ecnt[it];
    const int base = blockIdx.x * 16;
    if (base >= cnt) return;
    const int* rl = (it & 1) ? g_rlist1 : g_rlist0;
    int* rl_next  = (it & 1) ? g_rlist0 : g_rlist1;

    __shared__ __align__(16) float h1s[8192];
    __shared__ float red[128];
    __shared__ float pts[96];
    __shared__ float sdfv[32];
    __shared__ float sa[16], se[16];
    __shared__ float scs[16], sce[16];
    __shared__ int   srr[16], sus[16], sue[16];

    const int tid = threadIdx.x;
    const float b3v = b3[0];
    const int apply_lt = (it > 0) ? 1 : 0;

    if (tid < 16) {
        int i = base + tid;
        int valid = (i < cnt) ? 1 : 0;
        int r = rl[valid ? i : (cnt - 1)];
        float as = g_acc_s[r], ae = g_acc_e[r];
        int lt = apply_lt ? ((as < ae) ? 1 : 0) : 1;
        int us0 = g_unfin_s[r] & lt & valid;
        int ue0 = g_unfin_e[r] & lt & valid;

        float cs = us0 ? g_nsdf_s[r] : 0.f;
        cs = (cs <= SDF_T) ? 0.f : cs;
        int us = us0 & ((cs > SDF_T) ? 1 : 0);
        float ce = ue0 ? g_nsdf_e[r] : 0.f;
        ce = (ce <= SDF_T) ? 0.f : ce;
        int ue = ue0 & ((ce > SDF_T) ? 1 : 0);

        float nas = as + cs, nae = ae - ce;
        if (valid) {
            g_unfin_s[r] = us; g_unfin_e[r] = ue;
            g_csdf_s[r] = cs; g_csdf_e[r] = ce;
            g_acc_s[r] = nas; g_acc_e[r] = nae;
            if (us | ue) {
                int pos = atomicAdd(&g_ecnt[it + 1], 1);
                rl_next[pos] = r;
            }
        }
        sa[tid] = nas; se[tid] = nae;
        scs[tid] = cs; sce[tid] = ce;
        srr[tid] = valid ? r : -1;
        sus[tid] = us; sue[tid] = ue;
    }
    __syncthreads();
    if (tid < 32) {
        int g = tid >> 1;
        int r = srr[g]; if (r < 0) r = rl[cnt - 1];
        float a = (tid & 1) ? se[g] : sa[g];
        pts[tid*3+0] = fmaf(a, ray_in[r*3+0], cam_in[r*3+0]);
        pts[tid*3+1] = fmaf(a, ray_in[r*3+1], cam_in[r*3+1]);
        pts[tid*3+2] = fmaf(a, ray_in[r*3+2], cam_in[r*3+2]);
    }
    __syncthreads();
    sdf_eval32<512>(W1, b1, W2, b2, W3, b3v, pts, h1s, red, sdfv);
    if (tid < 16) {
        int r = srr[tid];
        if (r >= 0) {
            int nps = 0, npe = 0;
            if (sus[tid]) {
                float ns = sdfv[tid*2+0];
                g_nsdf_s[r] = ns;
                if (ns < 0.f) { nps = 1; g_acc_s[r] = sa[tid] - 0.5f * scs[tid]; }
            }
            if (sue[tid]) {
                float ne = sdfv[tid*2+1];
                g_nsdf_e[r] = ne;
                if (ne < 0.f) { npe = 1; g_acc_e[r] = se[tid] + 0.5f * sce[tid]; }
            }
            if (nps | npe) {
                int pos = atomicAdd(&g_ecnt[32 + it], 1);
                g_nplist[pos] = r | (nps << 16) | (npe << 17);
            }
        }
    }
}

// ---------------- E2: line-search re-eval over np rays (1024thr, latency-bound) ----------------
__global__ __launch_bounds__(1024)
void e2_kernel(const float* __restrict__ cam_in, const float* __restrict__ ray_in,
               const float* __restrict__ W1, const float* __restrict__ b1,
               const float* __restrict__ W2, const float* __restrict__ b2,
               const float* __restrict__ W3, const float* __restrict__ b3,
               int it)
{
    const int cnt = g_ecnt[32 + it];
    const int base = blockIdx.x * 16;
    if (base >= cnt) return;

    __shared__ __align__(16) float h1s[8192];
    __shared__ float red[128];
    __shared__ float pts[96];
    __shared__ float sdfv[32];
    __shared__ float sa[16], se[16];
    __shared__ int   sitem[16];

    const int tid = threadIdx.x;
    const float b3v = b3[0];

    if (tid < 16) {
        int i = base + tid;
        int valid = (i < cnt) ? 1 : 0;
        int item = g_nplist[valid ? i : (cnt - 1)];
        int r = item & 0xFFFF;
        sitem[tid] = valid ? item : -1;
        sa[tid] = g_acc_s[r];
        se[tid] = g_acc_e[r];
    }
    __syncthreads();
    if (tid < 32) {
        int g = tid >> 1;
        int item = sitem[g];
        int r = (item >= 0) ? (item & 0xFFFF) : (g_nplist[cnt - 1] & 0xFFFF);
        float a = (tid & 1) ? se[g] : sa[g];
        pts[tid*3+0] = fmaf(a, ray_in[r*3+0], cam_in[r*3+0]);
        pts[tid*3+1] = fmaf(a, ray_in[r*3+1], cam_in[r*3+1]);
        pts[tid*3+2] = fmaf(a, ray_in[r*3+2], cam_in[r*3+2]);
    }
    __syncthreads();
    sdf_eval32<1024>(W1, b1, W2, b2, W3, b3v, pts, h1s, red, sdfv);
    if (tid < 16) {
        int item = sitem[tid];
        if (item >= 0) {
            int r = item & 0xFFFF;
            if (item & 0x10000) g_nsdf_s[r] = sdfv[tid*2+0];
            if (item & 0x20000) g_nsdf_e[r] = sdfv[tid*2+1];
        }
    }
}

// ---------------- final: mask + defaults ----------------
__global__ __launch_bounds__(256)
void k_final(const float* __restrict__ cam_in, const float* __restrict__ ray_in,
             float* __restrict__ out, int R)
{
    int r = blockIdx.x * 256 + threadIdx.x;
    if (r >= R) return;
    float as = g_acc_s[r], ae = g_acc_e[r];
    int us = g_unfin_s[r] & ((as < ae) ? 1 : 0);
    float cs = us ? g_nsdf_s[r] : 0.f;
    cs = (cs <= SDF_T) ? 0.f : cs;
    int mask = us & ((cs > SDF_T) ? 1 : 0);
    g_smin[r] = as; g_smax[r] = ae;
    if (mask) {
        int pos = atomicAdd(&g_nmasked, 1);
        g_mlist[pos] = r;
    }
    float cx = cam_in[r*3+0], cy = cam_in[r*3+1], cz = cam_in[r*3+2];
    float rx = ray_in[r*3+0], ry = ray_in[r*3+1], rz = ray_in[r*3+2];
    out[r*3+0] = fmaf(as, rx, cx);
    out[r*3+1] = fmaf(as, ry, cy);
    out[r*3+2] = fmaf(as, rz, cz);
    out[R*3+r] = (as < ae) ? 1.f : 0.f;
    out[R*4+r] = as;
}

// ---------------- sampler prepass: 4 masked rays x 8 samples (512thr) ----------------
__global__ __launch_bounds__(512)
void prepass_kernel(const float* __restrict__ cam_in, const float* __restrict__ ray_in,
                    const float* __restrict__ W1, const float* __restrict__ b1,
                    const float* __restrict__ W2, const float* __restrict__ b2,
                    const float* __restrict__ W3, const float* __restrict__ b3)
{
    const int nmask = g_nmasked;
    const int g = blockIdx.x;
    if (g * 4 >= nmask) return;

    __shared__ __align__(16) float h1s[8192];
    __shared__ float red[128];
    __shared__ float pts[96];
    __shared__ float sdfv[32];

    const int tid = threadIdx.x;
    const float b3v = b3[0];
    if (tid < 32) {
        int li = g * 4 + (tid >> 3);
        int lic = (li < nmask) ? li : (nmask - 1);
        int r = g_mlist[lic];
        float smin = g_smin[r];
        float dz = g_smax[r] - smin;
        int i = tid & 7;
        float z = fmaf(dz, (float)i * INV99, smin);
        pts[tid*3+0] = fmaf(z, ray_in[r*3+0], cam_in[r*3+0]);
        pts[tid*3+1] = fmaf(z, ray_in[r*3+1], cam_in[r*3+1]);
        pts[tid*3+2] = fmaf(z, ray_in[r*3+2], cam_in[r*3+2]);
    }
    __syncthreads();
    sdf_eval32<512>(W1, b1, W2, b2, W3, b3v, pts, h1s, red, sdfv);
    if (tid < 32) {
        bool neg = (sdfv[tid] < 0.f);
        unsigned ball = __ballot_sync(0xffffffffu, neg);
        if ((tid & 7) == 0) {
            int j = tid >> 3;
            int li = g * 4 + j;
            if (li < nmask) {
                int r = g_mlist[li];
                unsigned sub = (ball >> (j * 8)) & 0xFFu;
                int q = sub ? (__ffs(sub) - 1) : 0;
                if (sub && q >= 1) {
                    float smin = g_smin[r];
                    float dz = g_smax[r] - smin;
                    float zlo = fmaf(dz, (float)(q - 1) * INV99, smin);
                    float zhi = fmaf(dz, (float)q * INV99, smin);
                    float slo = sdfv[j * 8 + q - 1];
                    float shi = sdfv[j * 8 + q];
                    float den = shi - slo; if (fabsf(den) <= 1e-12f) den = 1e-12f;
                    float zp = -slo * (zhi - zlo) / den + zlo;
                    g_zlo[r] = zlo; g_zhi[r] = zhi;
                    g_slo[r] = slo; g_shi[r] = shi; g_zp[r] = zp;
                    int pos = atomicAdd(&g_seccount, 1);
                    g_seclist[pos] = r;
                } else {
                    int pos = atomicAdd(&g_nfall, 1);
                    g_flist[pos] = r;
                }
            }
        }
    }
}

// ---------------- sampler fallback: full chunked scan (1024thr, few blocks) ----------------
__global__ __launch_bounds__(1024)
void fallback_kernel(const float* __restrict__ cam_in, const float* __restrict__ ray_in,
                     const float* __restrict__ W1, const float* __restrict__ b1,
                     const float* __restrict__ W2, const float* __restrict__ b2,
                     const float* __restrict__ W3, const float* __restrict__ b3,
                     float* __restrict__ out, int R)
{
    const int li = blockIdx.x;
    if (li >= g_nfall) return;
    const int r = g_flist[li];

    __shared__ __align__(16) float h1s[8192];
    __shared__ float red[128];
    __shared__ float pts[96];
    __shared__ float sdfv[32];
    __shared__ float s_all[100];
    __shared__ float s_cr[6];
    __shared__ int   s_found;

    const int tid = threadIdx.x;
    const float b3v = b3[0];
    if (tid < 6)
        s_cr[tid] = (tid < 3) ? cam_in[r * 3 + tid] : ray_in[r * 3 + tid - 3];
    if (tid == 0) s_found = -1;
    const float smin = g_smin[r];
    const float dz = g_smax[r] - smin;
    __syncthreads();

    for (int c = 0; c < 4; ++c) {
        const int cbase = c * 32;
        const int cnt = (100 - cbase < 32) ? (100 - cbase) : 32;
        if (tid < 32) {
            int i = cbase + tid; if (i > 99) i = 99;
            float z = fmaf(dz, (float)i * INV99, smin);
            pts[tid*3+0] = fmaf(z, s_cr[3], s_cr[0]);
            pts[tid*3+1] = fmaf(z, s_cr[4], s_cr[1]);
            pts[tid*3+2] = fmaf(z, s_cr[5], s_cr[2]);
        }
        __syncthreads();
        sdf_eval32<1024>(W1, b1, W2, b2, W3, b3v, pts, h1s, red, sdfv);
        if (tid < 32) {
            if (tid < cnt) s_all[cbase + tid] = sdfv[tid];
            bool neg = (tid < cnt) && (sdfv[tid] < 0.f);
            unsigned m = __ballot_sync(0xffffffffu, neg);
            if (tid == 0 && m) s_found = cbase + (__ffs(m) - 1);
        }
        __syncthreads();
        if (s_found >= 0) break;
    }

    if (tid == 0) {
        int ind;
        if (s_found >= 0) {
            ind = s_found;
        } else {
            ind = 99;
            for (int i = 0; i < 100; ++i)
                if (s_all[i] == 0.f) { ind = i; break; }
        }
        int il = (ind >= 1) ? (ind - 1) : 99;
        if (il > ind && s_found >= 0) il = 0;
        float zlo = fmaf(dz, (float)il  * INV99, smin);
        float zhi = fmaf(dz, (float)ind * INV99, smin);
        float slo = s_all[il], shi = s_all[ind];
        if (shi < 0.f) {
            float den = shi - slo; if (fabsf(den) <= 1e-12f) den = 1e-12f;
            float zp = -slo * (zhi - zlo) / den + zlo;
            g_zlo[r] = zlo; g_zhi[r] = zhi; g_slo[r] = slo; g_shi[r] = shi; g_zp[r] = zp;
            int pos = atomicAdd(&g_seccount, 1);
            g_seclist[pos] = r;
        } else {
            float dist = zhi;
            out[r*3+0] = fmaf(dist, s_cr[3], s_cr[0]);
            out[r*3+1] = fmaf(dist, s_cr[4], s_cr[1]);
            out[r*3+2] = fmaf(dist, s_cr[5], s_cr[2]);
            out[R*3+r] = 0.f;
            out[R*4+r] = dist;
        }
    }
}

// ---------------- batched secant: 32 rays per block (1024thr, latency-bound) ----------------
__global__ __launch_bounds__(1024)
void secant_kernel(const float* __restrict__ cam_in, const float* __restrict__ ray_in,
                   const float* __restrict__ W1, const float* __restrict__ b1,
                   const float* __restrict__ W2, const float* __restrict__ b2,
                   const float* __restrict__ W3, const float* __restrict__ b3,
                   float* __restrict__ out, int R)
{
    const int base = blockIdx.x * 32;
    if (base >= g_seccount) return;

    __shared__ __align__(16) float h1s[8192];
    __shared__ float red[128];
    __shared__ float pts[96];
    __shared__ float sdfv[32];
    __shared__ float s_cr[32][6];
    __shared__ float s_zlo[32], s_zhi[32], s_slo[32], s_shi[32], s_zp[32];
    __shared__ int   s_r[32];
    __shared__ int   s_n;

    const int tid = threadIdx.x;
    const float b3v = b3[0];
    if (tid == 0) {
        int c = g_seccount - base;
        s_n = (c < 32) ? c : 32;
    }
    __syncthreads();
    const int n = s_n;
    if (tid < 32) {
        int li = (tid < n) ? tid : 0;
        int r = g_seclist[base + li];
        s_r[tid] = (tid < n) ? r : -1;
        s_zlo[tid] = g_zlo[r]; s_zhi[tid] = g_zhi[r];
        s_slo[tid] = g_slo[r]; s_shi[tid] = g_shi[r];
        s_zp[tid]  = g_zp[r];
        s_cr[tid][0] = cam_in[r*3+0]; s_cr[tid][1] = cam_in[r*3+1]; s_cr[tid][2] = cam_in[r*3+2];
        s_cr[tid][3] = ray_in[r*3+0]; s_cr[tid][4] = ray_in[r*3+1]; s_cr[tid][5] = ray_in[r*3+2];
    }
    __syncthreads();

    for (int it = 0; it < 8; ++it) {
        if (tid < 32) {
            float zp = s_zp[tid];
            pts[tid*3+0] = fmaf(zp, s_cr[tid][3], s_cr[tid][0]);
            pts[tid*3+1] = fmaf(zp, s_cr[tid][4], s_cr[tid][1]);
            pts[tid*3+2] = fmaf(zp, s_cr[tid][5], s_cr[tid][2]);
        }
        __syncthreads();
        sdf_eval32<1024>(W1, b1, W2, b2, W3, b3v, pts, h1s, red, sdfv);
        if (tid < 32) {
            float mid = sdfv[tid];
            if (mid > 0.f) { s_zlo[tid] = s_zp[tid]; s_slo[tid] = mid; }
            if (mid < 0.f) { s_zhi[tid] = s_zp[tid]; s_shi[tid] = mid; }
            float den = s_shi[tid] - s_slo[tid];
            if (fabsf(den) <= 1e-12f) den = 1e-12f;
            s_zp[tid] = -s_slo[tid] * (s_zhi[tid] - s_zlo[tid]) / den + s_zlo[tid];
        }
        __syncthreads();
    }

    if (tid < n) {
        int r = s_r[tid];
        float dist = s_zp[tid];
        out[r*3+0] = fmaf(dist, s_cr[tid][3], s_cr[tid][0]);
        out[r*3+1] = fmaf(dist, s_cr[tid][4], s_cr[tid][1]);
        out[r*3+2] = fmaf(dist, s_cr[tid][5], s_cr[tid][2]);
        out[R*3+r] = 1.f;
        out[R*4+r] = dist;
    }
}

// ---------------- launch ----------------
extern "C" void kernel_launch(void* const* d_in, const int* in_sizes, int n_in,
                              void* d_out, int out_size)
{
    const float* cam  = (const float*)d_in[0];
    const float* rays = (const float*)d_in[1];
    // d_in[2] = object_mask (unused by the eval-mode forward)
    const float* W1 = (const float*)d_in[3];
    const float* b1 = (const float*)d_in[4];
    const float* W2 = (const float*)d_in[5];
    const float* b2 = (const float*)d_in[6];
    const float* W3 = (const float*)d_in[7];
    const float* b3 = (const float*)d_in[8];
    int R = in_sizes[0] / 3;
    if (R > RMAX) R = RMAX;
    float* out = (float*)d_out;

    const int nb  = (R + 255) / 256;
    const int n16 = (R + 15) / 16;

    init_kernel<<<1, 128>>>();
    k1_init_eval<<<n16, 512>>>(cam, rays, W1, b1, W2, b2, W3, b3, R);
    for (int it = 0; it < 10; ++it) {
        e1_kernel<<<n16, 512>>>(cam, rays, W1, b1, W2, b2, W3, b3, it);
        e2_kernel<<<n16, 1024>>>(cam, rays, W1, b1, W2, b2, W3, b3, it);
    }
    k_final<<<nb, 256>>>(cam, rays, out, R);
    prepass_kernel<<<(R + 3) / 4, 512>>>(cam, rays, W1, b1, W2, b2, W3, b3);
    fallback_kernel<<<R, 1024>>>(cam, rays, W1, b1, W2, b2, W3, b3, out, R);
    secant_kernel<<<(R + 31) / 32, 1024>>>(cam, rays, W1, b1, W2, b2, W3, b3, out, R);
}

// round 16
// speedup vs baseline: 1.5573x; 1.4788x over previous
#include <cuda_runtime.h>
#include <math.h>

// ---------------- constants ----------------
#define RMAX 8192
static constexpr float SDF_T = 5e-05f;
static constexpr float INV99 = 1.0f / 99.0f;

// ---------------- inter-kernel scratch ----------------
__device__ float g_acc_s[RMAX], g_acc_e[RMAX];
__device__ float g_nsdf_s[RMAX], g_nsdf_e[RMAX];
__device__ float g_csdf_s[RMAX], g_csdf_e[RMAX];
__device__ int   g_unfin_s[RMAX], g_unfin_e[RMAX];
__device__ float g_smin[RMAX], g_smax[RMAX];
__device__ int   g_mlist[RMAX];
__device__ int   g_nmasked;
__device__ int   g_flist[RMAX];
__device__ int   g_nfall;
__device__ int   g_seclist[RMAX];
__device__ int   g_seccount;
__device__ float g_zlo[RMAX], g_zhi[RMAX], g_slo[RMAX], g_shi[RMAX], g_zp[RMAX];
__device__ int   g_rlist0[RMAX];
__device__ int   g_rlist1[RMAX];
__device__ int   g_nplist[RMAX];
__device__ int   g_ecnt[64];

__global__ void init_kernel() {
    int t = threadIdx.x;
    if (t < 64) g_ecnt[t] = 0;
    if (t == 64) g_nmasked = 0;
    if (t == 65) g_seccount = 0;
    if (t == 66) g_nfall = 0;
}

// ---------------- f32x2 helpers ----------------
__device__ __forceinline__ unsigned long long pack2(float a, float b) {
    unsigned long long r;
    asm("mov.b64 %0, {%1, %2};" : "=l"(r) : "f"(a), "f"(b));
    return r;
}
__device__ __forceinline__ void unpack2(unsigned long long v, float& a, float& b) {
    asm("mov.b64 {%0, %1}, %2;" : "=f"(a), "=f"(b) : "l"(v));
}
__device__ __forceinline__ unsigned long long fma2(unsigned long long a,
                                                   unsigned long long b,
                                                   unsigned long long c) {
    unsigned long long d;
    asm("fma.rn.f32x2 %0, %1, %2, %3;" : "=l"(d) : "l"(a), "l"(b), "l"(c));
    return d;
}
__device__ __forceinline__ unsigned long long add2(unsigned long long a,
                                                   unsigned long long b) {
    unsigned long long d;
    asm("add.rn.f32x2 %0, %1, %2;" : "=l"(d) : "l"(a), "l"(b));
    return d;
}

// HW tanh approximation (sm_75+): single MUFU op, rel err ~5e-4.
// Error propagated through the 0.05-scaled MLP term stays ~1e-4 << 1e-3 gate.
__device__ __forceinline__ float tanh_fast(float x) {
    float y;
    asm("tanh.approx.f32 %0, %1;" : "=f"(y) : "f"(x));
    return y;
}

// ---------------- batched SDF eval, P = 32 points, 512 threads ----------------
// thread = (neuron pair npair) x (point half) x (k half). Serial k loop: 64 iters.
// k-half partials combined via add.rn.f32x2 through smem (h1s reused).
__device__ __forceinline__ void sdf_eval32(
    const float* __restrict__ W1, const float* __restrict__ b1,
    const float* __restrict__ W2, const float* __restrict__ b2,
    const float* __restrict__ W3, float b3v,
    const float* pts, float* h1s, float* red, float* sdfv)
{
    const int tid = threadIdx.x;

    // ---- layer 1: 8192 entries / 512 threads = 16 iters ----
#pragma unroll
    for (int it = 0; it < 16; ++it) {
        int idx = it * 512 + tid;
        int k = idx >> 5;
        int p = idx & 31;
        float x = pts[p * 3 + 0], y = pts[p * 3 + 1], z = pts[p * 3 + 2];
        float v = fmaf(W1[k], x, fmaf(W1[256 + k], y, fmaf(W1[512 + k], z, b1[k])));
        h1s[idx] = tanh_fast(v);
    }
    __syncthreads();

    // ---- layer 2 ----
    const int khalf = tid >> 8;          // 0: k in [0,128), 1: k in [128,256)
    const int rem   = tid & 255;
    const int half  = rem >> 7;          // point half
    const int npair = rem & 127;         // neurons 2*npair, 2*npair+1
    unsigned long long accA[8], accB[8];
#pragma unroll
    for (int q = 0; q < 8; ++q) { accA[q] = 0ull; accB[q] = 0ull; }

    const float2* W2p = reinterpret_cast<const float2*>(W2) + npair;
    const float* hbase = h1s + half * 16;
    const int kbase = khalf << 7;
    const int kend  = kbase + 128;

    float2 w0[2], w1[2];
#pragma unroll
    for (int u = 0; u < 2; ++u) w0[u] = W2p[(kbase + u) * 128];
#pragma unroll
    for (int u = 0; u < 2; ++u) w1[u] = W2p[(kbase + 2 + u) * 128];

#pragma unroll 1
    for (int k0 = kbase; k0 < kend; k0 += 2) {
        float2 wn[2];
        int kp = k0 + 4;
        if (kp < kend) {
#pragma unroll
            for (int u = 0; u < 2; ++u) wn[u] = W2p[(kp + u) * 128];
        } else {
#pragma unroll
            for (int u = 0; u < 2; ++u) wn[u] = make_float2(0.f, 0.f);
        }
#pragma unroll
        for (int u = 0; u < 2; ++u) {
            unsigned long long wA = pack2(w0[u].x, w0[u].x);
            unsigned long long wB = pack2(w0[u].y, w0[u].y);
            const ulonglong2* h2 =
                reinterpret_cast<const ulonglong2*>(hbase + (k0 + u) * 32);
            ulonglong2 v0 = h2[0], v1 = h2[1], v2 = h2[2], v3 = h2[3];
            accA[0] = fma2(v0.x, wA, accA[0]); accB[0] = fma2(v0.x, wB, accB[0]);
            accA[1] = fma2(v0.y, wA, accA[1]); accB[1] = fma2(v0.y, wB, accB[1]);
            accA[2] = fma2(v1.x, wA, accA[2]); accB[2] = fma2(v1.x, wB, accB[2]);
            accA[3] = fma2(v1.y, wA, accA[3]); accB[3] = fma2(v1.y, wB, accB[3]);
            accA[4] = fma2(v2.x, wA, accA[4]); accB[4] = fma2(v2.x, wB, accB[4]);
            accA[5] = fma2(v2.y, wA, accA[5]); accB[5] = fma2(v2.y, wB, accB[5]);
            accA[6] = fma2(v3.x, wA, accA[6]); accB[6] = fma2(v3.x, wB, accB[6]);
            accA[7] = fma2(v3.y, wA, accA[7]); accB[7] = fma2(v3.y, wB, accB[7]);
        }
#pragma unroll
        for (int u = 0; u < 2; ++u) { w0[u] = w1[u]; w1[u] = wn[u]; }
    }

    // ---- combine k-halves through smem (h1s no longer needed) ----
    __syncthreads();
    unsigned long long* part = reinterpret_cast<unsigned long long*>(h1s);
    if (khalf == 1) {
#pragma unroll
        for (int q = 0; q < 8; ++q) {
            part[q * 256 + rem]       = accA[q];
            part[(8 + q) * 256 + rem] = accB[q];
        }
    }
    __syncthreads();

    if (khalf == 0) {
#pragma unroll
        for (int q = 0; q < 8; ++q) {
            accA[q] = add2(accA[q], part[q * 256 + rem]);
            accB[q] = add2(accB[q], part[(8 + q) * 256 + rem]);
        }

        // ---- layer 3 (threads 0..255 only; full warps) ----
        float2 b2v = reinterpret_cast<const float2*>(b2)[npair];
        float2 w3j = reinterpret_cast<const float2*>(W3)[npair];
        const int sub = (rem >> 5) & 3;
#pragma unroll
        for (int q = 0; q < 8; ++q) {
            float a0, a1, c0, c1;
            unpack2(accA[q], a0, a1);
            unpack2(accB[q], c0, c1);
            float m0 = tanh_fast(a0 + b2v.x) * w3j.x + tanh_fast(c0 + b2v.y) * w3j.y;
            float m1 = tanh_fast(a1 + b2v.x) * w3j.x + tanh_fast(c1 + b2v.y) * w3j.y;
#pragma unroll
            for (int off = 16; off; off >>= 1) {
                m0 += __shfl_down_sync(0xffffffffu, m0, off);
                m1 += __shfl_down_sync(0xffffffffu, m1, off);
            }
            if ((rem & 31) == 0) {
                int p0 = half * 16 + 2 * q;
                red[p0 * 4 + sub] = m0;
                red[(p0 + 1) * 4 + sub] = m1;
            }
        }
    }
    __syncthreads();
    if (tid < 32) {
        float s = red[tid * 4 + 0] + red[tid * 4 + 1] + red[tid * 4 + 2] + red[tid * 4 + 3];
        float x = pts[tid * 3 + 0], y = pts[tid * 3 + 1], z = pts[tid * 3 + 2];
        float base = sqrtf(fmaf(x, x, fmaf(y, y, fmaf(z, z, 1e-12f)))) - 0.6f;
        sdfv[tid] = base + 0.05f * (s + b3v);
    }
    __syncthreads();
}

// ---------------- K1: ray init + eval both endpoints + seed list0 ----------------
__global__ __launch_bounds__(512)
void k1_init_eval(const float* __restrict__ cam_in, const float* __restrict__ ray_in,
                  const float* __restrict__ W1, const float* __restrict__ b1,
                  const float* __restrict__ W2, const float* __restrict__ b2,
                  const float* __restrict__ W3, const float* __restrict__ b3,
                  int R)
{
    __shared__ __align__(16) float h1s[8192];
    __shared__ float red[128];
    __shared__ float pts[96];
    __shared__ float sdfv[32];
    __shared__ float sa[16], se[16];
    __shared__ int   srm[16];

    const int tid = threadIdx.x;
    const int base = blockIdx.x * 16;
    const float b3v = b3[0];

    if (tid < 16) {
        int r = base + tid;
        int rc = (r < R) ? r : (R - 1);
        float cx = cam_in[rc*3+0], cy = cam_in[rc*3+1], cz = cam_in[rc*3+2];
        float rx = ray_in[rc*3+0], ry = ray_in[rc*3+1], rz = ray_in[rc*3+2];
        float dt = rx*cx + ry*cy + rz*cz;
        float cc = cx*cx + cy*cy + cz*cz;
        float under = dt*dt - (cc - 1.0f);
        int mi = (under > 0.f) ? 1 : 0;
        float sq = sqrtf(mi ? under : 1.0f);
        float i0 = mi ? fmaxf(-sq - dt, 0.f) : 0.f;
        float i1 = mi ? fmaxf( sq - dt, 0.f) : 0.f;
        if (r < R) {
            g_acc_s[r] = i0; g_acc_e[r] = i1;
            g_unfin_s[r] = mi; g_unfin_e[r] = mi;
            g_nsdf_s[r] = 0.f; g_nsdf_e[r] = 0.f;
            if (mi) {
                int pos = atomicAdd(&g_ecnt[0], 1);
                g_rlist0[pos] = r;
            }
        }
        sa[tid] = i0; se[tid] = i1;
        srm[tid] = (r < R && mi) ? r : -1;
    }
    __syncthreads();
    if (tid < 32) {
        int g = tid >> 1;
        int r = base + g; if (r >= R) r = R - 1;
        float a = (tid & 1) ? se[g] : sa[g];
        pts[tid*3+0] = fmaf(a, ray_in[r*3+0], cam_in[r*3+0]);
        pts[tid*3+1] = fmaf(a, ray_in[r*3+1], cam_in[r*3+1]);
        pts[tid*3+2] = fmaf(a, ray_in[r*3+2], cam_in[r*3+2]);
    }
    __syncthreads();
    sdf_eval32(W1, b1, W2, b2, W3, b3v, pts, h1s, red, sdfv);
    if (tid < 16) {
        int r = srm[tid];
        if (r >= 0) {
            g_nsdf_s[r] = sdfv[tid * 2 + 0];
            g_nsdf_e[r] = sdfv[tid * 2 + 1];
        }
    }
}

// ---------------- E1: gating + advance + eval + np backstep ----------------
__global__ __launch_bounds__(512)
void e1_kernel(const float* __restrict__ cam_in, const float* __restrict__ ray_in,
               const float* __restrict__ W1, const float* __restrict__ b1,
               const float* __restrict__ W2, const float* __restrict__ b2,
               const float* __restrict__ W3, const float* __restrict__ b3,
               int it)
{
    const int cnt = g_ecnt[it];
    const int base = blockIdx.x * 16;
    if (base >= cnt) return;
    const int* rl = (it & 1) ? g_rlist1 : g_rlist0;
    int* rl_next  = (it & 1) ? g_rlist0 : g_rlist1;

    __shared__ __align__(16) float h1s[8192];
    __shared__ float red[128];
    __shared__ float pts[96];
    __shared__ float sdfv[32];
    __shared__ float sa[16], se[16];
    __shared__ float scs[16], sce[16];
    __shared__ int   srr[16], sus[16], sue[16];

    const int tid = threadIdx.x;
    const float b3v = b3[0];
    const int apply_lt = (it > 0) ? 1 : 0;

    if (tid < 16) {
        int i = base + tid;
        int valid = (i < cnt) ? 1 : 0;
        int r = rl[valid ? i : (cnt - 1)];
        float as = g_acc_s[r], ae = g_acc_e[r];
        int lt = apply_lt ? ((as < ae) ? 1 : 0) : 1;
        int us0 = g_unfin_s[r] & lt & valid;
        int ue0 = g_unfin_e[r] & lt & valid;

        float cs = us0 ? g_nsdf_s[r] : 0.f;
        cs = (cs <= SDF_T) ? 0.f : cs;
        int us = us0 & ((cs > SDF_T) ? 1 : 0);
        float ce = ue0 ? g_nsdf_e[r] : 0.f;
        ce = (ce <= SDF_T) ? 0.f : ce;
        int ue = ue0 & ((ce > SDF_T) ? 1 : 0);

        float nas = as + cs, nae = ae - ce;
        if (valid) {
            g_unfin_s[r] = us; g_unfin_e[r] = ue;
            g_csdf_s[r] = cs; g_csdf_e[r] = ce;
            g_acc_s[r] = nas; g_acc_e[r] = nae;
            if (us | ue) {
                int pos = atomicAdd(&g_ecnt[it + 1], 1);
                rl_next[pos] = r;
            }
        }
        sa[tid] = nas; se[tid] = nae;
        scs[tid] = cs; sce[tid] = ce;
        srr[tid] = valid ? r : -1;
        sus[tid] = us; sue[tid] = ue;
    }
    __syncthreads();
    if (tid < 32) {
        int g = tid >> 1;
        int r = srr[g]; if (r < 0) r = rl[cnt - 1];
        float a = (tid & 1) ? se[g] : sa[g];
        pts[tid*3+0] = fmaf(a, ray_in[r*3+0], cam_in[r*3+0]);
        pts[tid*3+1] = fmaf(a, ray_in[r*3+1], cam_in[r*3+1]);
        pts[tid*3+2] = fmaf(a, ray_in[r*3+2], cam_in[r*3+2]);
    }
    __syncthreads();
    sdf_eval32(W1, b1, W2, b2, W3, b3v, pts, h1s, red, sdfv);
    if (tid < 16) {
        int r = srr[tid];
        if (r >= 0) {
            int nps = 0, npe = 0;
            if (sus[tid]) {
                float ns = sdfv[tid*2+0];
                g_nsdf_s[r] = ns;
                if (ns < 0.f) { nps = 1; g_acc_s[r] = sa[tid] - 0.5f * scs[tid]; }
            }
            if (sue[tid]) {
                float ne = sdfv[tid*2+1];
                g_nsdf_e[r] = ne;
                if (ne < 0.f) { npe = 1; g_acc_e[r] = se[tid] + 0.5f * sce[tid]; }
            }
            if (nps | npe) {
                int pos = atomicAdd(&g_ecnt[32 + it], 1);
                g_nplist[pos] = r | (nps << 16) | (npe << 17);
            }
        }
    }
}

// ---------------- E2: line-search re-eval over np rays ----------------
__global__ __launch_bounds__(512)
void e2_kernel(const float* __restrict__ cam_in, const float* __restrict__ ray_in,
               const float* __restrict__ W1, const float* __restrict__ b1,
               const float* __restrict__ W2, const float* __restrict__ b2,
               const float* __restrict__ W3, const float* __restrict__ b3,
               int it)
{
    const int cnt = g_ecnt[32 + it];
    const int base = blockIdx.x * 16;
    if (base >= cnt) return;

    __shared__ __align__(16) float h1s[8192];
    __shared__ float red[128];
    __shared__ float pts[96];
    __shared__ float sdfv[32];
    __shared__ float sa[16], se[16];
    __shared__ int   sitem[16];

    const int tid = threadIdx.x;
    const float b3v = b3[0];

    if (tid < 16) {
        int i = base + tid;
        int valid = (i < cnt) ? 1 : 0;
        int item = g_nplist[valid ? i : (cnt - 1)];
        int r = item & 0xFFFF;
        sitem[tid] = valid ? item : -1;
        sa[tid] = g_acc_s[r];
        se[tid] = g_acc_e[r];
    }
    __syncthreads();
    if (tid < 32) {
        int g = tid >> 1;
        int item = sitem[g];
        int r = (item >= 0) ? (item & 0xFFFF) : (g_nplist[cnt - 1] & 0xFFFF);
        float a = (tid & 1) ? se[g] : sa[g];
        pts[tid*3+0] = fmaf(a, ray_in[r*3+0], cam_in[r*3+0]);
        pts[tid*3+1] = fmaf(a, ray_in[r*3+1], cam_in[r*3+1]);
        pts[tid*3+2] = fmaf(a, ray_in[r*3+2], cam_in[r*3+2]);
    }
    __syncthreads();
    sdf_eval32(W1, b1, W2, b2, W3, b3v, pts, h1s, red, sdfv);
    if (tid < 16) {
        int item = sitem[tid];
        if (item >= 0) {
            int r = item & 0xFFFF;
            if (item & 0x10000) g_nsdf_s[r] = sdfv[tid*2+0];
            if (item & 0x20000) g_nsdf_e[r] = sdfv[tid*2+1];
        }
    }
}

// ---------------- final: mask + defaults ----------------
__global__ __launch_bounds__(256)
void k_final(const float* __restrict__ cam_in, const float* __restrict__ ray_in,
             float* __restrict__ out, int R)
{
    int r = blockIdx.x * 256 + threadIdx.x;
    if (r >= R) return;
    float as = g_acc_s[r], ae = g_acc_e[r];
    int us = g_unfin_s[r] & ((as < ae) ? 1 : 0);
    float cs = us ? g_nsdf_s[r] : 0.f;
    cs = (cs <= SDF_T) ? 0.f : cs;
    int mask = us & ((cs > SDF_T) ? 1 : 0);
    g_smin[r] = as; g_smax[r] = ae;
    if (mask) {
        int pos = atomicAdd(&g_nmasked, 1);
        g_mlist[pos] = r;
    }
    float cx = cam_in[r*3+0], cy = cam_in[r*3+1], cz = cam_in[r*3+2];
    float rx = ray_in[r*3+0], ry = ray_in[r*3+1], rz = ray_in[r*3+2];
    out[r*3+0] = fmaf(as, rx, cx);
    out[r*3+1] = fmaf(as, ry, cy);
    out[r*3+2] = fmaf(as, rz, cz);
    out[R*3+r] = (as < ae) ? 1.f : 0.f;
    out[R*4+r] = as;
}

// ---------------- sampler prepass: 4 masked rays x 8 samples per eval ----------------
__global__ __launch_bounds__(512)
void prepass_kernel(const float* __restrict__ cam_in, const float* __restrict__ ray_in,
                    const float* __restrict__ W1, const float* __restrict__ b1,
                    const float* __restrict__ W2, const float* __restrict__ b2,
                    const float* __restrict__ W3, const float* __restrict__ b3)
{
    const int nmask = g_nmasked;
    const int g = blockIdx.x;
    if (g * 4 >= nmask) return;

    __shared__ __align__(16) float h1s[8192];
    __shared__ float red[128];
    __shared__ float pts[96];
    __shared__ float sdfv[32];

    const int tid = threadIdx.x;
    const float b3v = b3[0];
    if (tid < 32) {
        int li = g * 4 + (tid >> 3);
        int lic = (li < nmask) ? li : (nmask - 1);
        int r = g_mlist[lic];
        float smin = g_smin[r];
        float dz = g_smax[r] - smin;
        int i = tid & 7;
        float z = fmaf(dz, (float)i * INV99, smin);
        pts[tid*3+0] = fmaf(z, ray_in[r*3+0], cam_in[r*3+0]);
        pts[tid*3+1] = fmaf(z, ray_in[r*3+1], cam_in[r*3+1]);
        pts[tid*3+2] = fmaf(z, ray_in[r*3+2], cam_in[r*3+2]);
    }
    __syncthreads();
    sdf_eval32(W1, b1, W2, b2, W3, b3v, pts, h1s, red, sdfv);
    if (tid < 32) {
        bool neg = (sdfv[tid] < 0.f);
        unsigned ball = __ballot_sync(0xffffffffu, neg);
        if ((tid & 7) == 0) {
            int j = tid >> 3;
            int li = g * 4 + j;
            if (li < nmask) {
                int r = g_mlist[li];
                unsigned sub = (ball >> (j * 8)) & 0xFFu;
                int q = sub ? (__ffs(sub) - 1) : 0;
                if (sub && q >= 1) {
                    float smin = g_smin[r];
                    float dz = g_smax[r] - smin;
                    float zlo = fmaf(dz, (float)(q - 1) * INV99, smin);
                    float zhi = fmaf(dz, (float)q * INV99, smin);
                    float slo = sdfv[j * 8 + q - 1];
                    float shi = sdfv[j * 8 + q];
                    float den = shi - slo; if (fabsf(den) <= 1e-12f) den = 1e-12f;
                    float zp = -slo * (zhi - zlo) / den + zlo;
                    g_zlo[r] = zlo; g_zhi[r] = zhi;
                    g_slo[r] = slo; g_shi[r] = shi; g_zp[r] = zp;
                    int pos = atomicAdd(&g_seccount, 1);
                    g_seclist[pos] = r;
                } else {
                    int pos = atomicAdd(&g_nfall, 1);
                    g_flist[pos] = r;
                }
            }
        }
    }
}

// ---------------- sampler fallback: full chunked scan ----------------
__global__ __launch_bounds__(512)
void fallback_kernel(const float* __restrict__ cam_in, const float* __restrict__ ray_in,
                     const float* __restrict__ W1, const float* __restrict__ b1,
                     const float* __restrict__ W2, const float* __restrict__ b2,
                     const float* __restrict__ W3, const float* __restrict__ b3,
                     float* __restrict__ out, int R)
{
    const int li = blockIdx.x;
    if (li >= g_nfall) return;
    const int r = g_flist[li];

    __shared__ __align__(16) float h1s[8192];
    __shared__ float red[128];
    __shared__ float pts[96];
    __shared__ float sdfv[32];
    __shared__ float s_all[100];
    __shared__ float s_cr[6];
    __shared__ int   s_found;

    const int tid = threadIdx.x;
    const float b3v = b3[0];
    if (tid < 6)
        s_cr[tid] = (tid < 3) ? cam_in[r * 3 + tid] : ray_in[r * 3 + tid - 3];
    if (tid == 0) s_found = -1;
    const float smin = g_smin[r];
    const float dz = g_smax[r] - smin;
    __syncthreads();

    for (int c = 0; c < 4; ++c) {
        const int cbase = c * 32;
        const int cnt = (100 - cbase < 32) ? (100 - cbase) : 32;
        if (tid < 32) {
            int i = cbase + tid; if (i > 99) i = 99;
            float z = fmaf(dz, (float)i * INV99, smin);
            pts[tid*3+0] = fmaf(z, s_cr[3], s_cr[0]);
            pts[tid*3+1] = fmaf(z, s_cr[4], s_cr[1]);
            pts[tid*3+2] = fmaf(z, s_cr[5], s_cr[2]);
        }
        __syncthreads();
        sdf_eval32(W1, b1, W2, b2, W3, b3v, pts, h1s, red, sdfv);
        if (tid < 32) {
            if (tid < cnt) s_all[cbase + tid] = sdfv[tid];
            bool neg = (tid < cnt) && (sdfv[tid] < 0.f);
            unsigned m = __ballot_sync(0xffffffffu, neg);
            if (tid == 0 && m) s_found = cbase + (__ffs(m) - 1);
        }
        __syncthreads();
        if (s_found >= 0) break;
    }

    if (tid == 0) {
        int ind;
        if (s_found >= 0) {
            ind = s_found;
        } else {
            ind = 99;
            for (int i = 0; i < 100; ++i)
                if (s_all[i] == 0.f) { ind = i; break; }
        }
        int il = (ind >= 1) ? (ind - 1) : 99;
        if (il > ind && s_found >= 0) il = 0;
        float zlo = fmaf(dz, (float)il  * INV99, smin);
        float zhi = fmaf(dz, (float)ind * INV99, smin);
        float slo = s_all[il], shi = s_all[ind];
        if (shi < 0.f) {
            float den = shi - slo; if (fabsf(den) <= 1e-12f) den = 1e-12f;
            float zp = -slo * (zhi - zlo) / den + zlo;
            g_zlo[r] = zlo; g_zhi[r] = zhi; g_slo[r] = slo; g_shi[r] = shi; g_zp[r] = zp;
            int pos = atomicAdd(&g_seccount, 1);
            g_seclist[pos] = r;
        } else {
            float dist = zhi;
            out[r*3+0] = fmaf(dist, s_cr[3], s_cr[0]);
            out[r*3+1] = fmaf(dist, s_cr[4], s_cr[1]);
            out[r*3+2] = fmaf(dist, s_cr[5], s_cr[2]);
            out[R*3+r] = 0.f;
            out[R*4+r] = dist;
        }
    }
}

// ---------------- batched secant: 32 rays per block ----------------
__global__ __launch_bounds__(512)
void secant_kernel(const float* __restrict__ cam_in, const float* __restrict__ ray_in,
                   const float* __restrict__ W1, const float* __restrict__ b1,
                   const float* __restrict__ W2, const float* __restrict__ b2,
                   const float* __restrict__ W3, const float* __restrict__ b3,
                   float* __restrict__ out, int R)
{
    const int base = blockIdx.x * 32;
    if (base >= g_seccount) return;

    __shared__ __align__(16) float h1s[8192];
    __shared__ float red[128];
    __shared__ float pts[96];
    __shared__ float sdfv[32];
    __shared__ float s_cr[32][6];
    __shared__ float s_zlo[32], s_zhi[32], s_slo[32], s_shi[32], s_zp[32];
    __shared__ int   s_r[32];
    __shared__ int   s_n;

    const int tid = threadIdx.x;
    const float b3v = b3[0];
    if (tid == 0) {
        int c = g_seccount - base;
        s_n = (c < 32) ? c : 32;
    }
    __syncthreads();
    const int n = s_n;
    if (tid < 32) {
        int li = (tid < n) ? tid : 0;
        int r = g_seclist[base + li];
        s_r[tid] = (tid < n) ? r : -1;
        s_zlo[tid] = g_zlo[r]; s_zhi[tid] = g_zhi[r];
        s_slo[tid] = g_slo[r]; s_shi[tid] = g_shi[r];
        s_zp[tid]  = g_zp[r];
        s_cr[tid][0] = cam_in[r*3+0]; s_cr[tid][1] = cam_in[r*3+1]; s_cr[tid][2] = cam_in[r*3+2];
        s_cr[tid][3] = ray_in[r*3+0]; s_cr[tid][4] = ray_in[r*3+1]; s_cr[tid][5] = ray_in[r*3+2];
    }
    __syncthreads();

    for (int it = 0; it < 8; ++it) {
        if (tid < 32) {
            float zp = s_zp[tid];
            pts[tid*3+0] = fmaf(zp, s_cr[tid][3], s_cr[tid][0]);
            pts[tid*3+1] = fmaf(zp, s_cr[tid][4], s_cr[tid][1]);
            pts[tid*3+2] = fmaf(zp, s_cr[tid][5], s_cr[tid][2]);
        }
        __syncthreads();
        sdf_eval32(W1, b1, W2, b2, W3, b3v, pts, h1s, red, sdfv);
        if (tid < 32) {
            float mid = sdfv[tid];
            if (mid > 0.f) { s_zlo[tid] = s_zp[tid]; s_slo[tid] = mid; }
            if (mid < 0.f) { s_zhi[tid] = s_zp[tid]; s_shi[tid] = mid; }
            float den = s_shi[tid] - s_slo[tid];
            if (fabsf(den) <= 1e-12f) den = 1e-12f;
            s_zp[tid] = -s_slo[tid] * (s_zhi[tid] - s_zlo[tid]) / den + s_zlo[tid];
        }
        __syncthreads();
    }

    if (tid < n) {
        int r = s_r[tid];
        float dist = s_zp[tid];
        out[r*3+0] = fmaf(dist, s_cr[tid][3], s_cr[tid][0]);
        out[r*3+1] = fmaf(dist, s_cr[tid][4], s_cr[tid][1]);
        out[r*3+2] = fmaf(dist, s_cr[tid][5], s_cr[tid][2]);
        out[R*3+r] = 1.f;
        out[R*4+r] = dist;
    }
}

// ---------------- launch ----------------
extern "C" void kernel_launch(void* const* d_in, const int* in_sizes, int n_in,
                              void* d_out, int out_size)
{
    const float* cam  = (const float*)d_in[0];
    const float* rays = (const float*)d_in[1];
    // d_in[2] = object_mask (unused by the eval-mode forward)
    const float* W1 = (const float*)d_in[3];
    const float* b1 = (const float*)d_in[4];
    const float* W2 = (const float*)d_in[5];
    const float* b2 = (const float*)d_in[6];
    const float* W3 = (const float*)d_in[7];
    const float* b3 = (const float*)d_in[8];
    int R = in_sizes[0] / 3;
    if (R > RMAX) R = RMAX;
    float* out = (float*)d_out;

    const int nb  = (R + 255) / 256;
    const int n16 = (R + 15) / 16;

    init_kernel<<<1, 128>>>();
    k1_init_eval<<<n16, 512>>>(cam, rays, W1, b1, W2, b2, W3, b3, R);
    for (int it = 0; it < 10; ++it) {
        e1_kernel<<<n16, 512>>>(cam, rays, W1, b1, W2, b2, W3, b3, it);
        e2_kernel<<<n16, 512>>>(cam, rays, W1, b1, W2, b2, W3, b3, it);
    }
    k_final<<<nb, 256>>>(cam, rays, out, R);
    prepass_kernel<<<(R + 3) / 4, 512>>>(cam, rays, W1, b1, W2, b2, W3, b3);
    fallback_kernel<<<R, 512>>>(cam, rays, W1, b1, W2, b2, W3, b3, out, R);
    secant_kernel<<<(R + 31) / 32, 512>>>(cam, rays, W1, b1, W2, b2, W3, b3, out, R);
}